// round 1
// baseline (speedup 1.0000x reference)
#include <cuda_runtime.h>
#include <math.h>

// ---------------- problem constants ----------------
#define Bsz   16
#define Nseq  784
#define DIM   512
#define Hh    8
#define KDIM  64
#define VDIM  256
#define RESW  28
#define QKVO  3072      // (2*64+256)*8
#define Mrows (Bsz*Nseq) // 12544
#define EPSV  1e-5f
#define SCALEV 0.125f    // 64^-0.5

// ---------------- scratch (device globals; no allocs allowed) ----------------
__device__ float g_Q[(size_t)Bsz*Hh*Nseq*KDIM];   // 25.7 MB
__device__ float g_K[(size_t)Bsz*Hh*Nseq*KDIM];   // 25.7 MB
__device__ float g_V[(size_t)Bsz*Hh*Nseq*VDIM];   // 102.8 MB
__device__ float g_AO[(size_t)Bsz*Nseq*Hh*VDIM];  // 102.8 MB

// =====================================================================
// GEMM 1: qkv = BN(x @ qkv_w^T), scattered into Q/K/V [B,H,N,D] layouts
// C[m,o] = sum_c A[m,c]*W[o,c];  M=12544, N=3072, K=512
// 128x128 tile, BK=16, 256 threads, 8x8 microtile
// =====================================================================
__global__ __launch_bounds__(256) void gemm_qkv_kernel(
    const float* __restrict__ A, const float* __restrict__ W,
    const float* __restrict__ gamma, const float* __restrict__ beta,
    const float* __restrict__ mean, const float* __restrict__ var)
{
    __shared__ float As[16][132];
    __shared__ float Ws[16][132];
    const int K = DIM;
    int bm = blockIdx.x * 128;
    int bn = blockIdx.y * 128;
    int tid = threadIdx.x;
    int trow = (tid >> 4) << 3;
    int tcol = (tid & 15) << 3;

    float acc[8][8];
#pragma unroll
    for (int i = 0; i < 8; i++)
#pragma unroll
        for (int j = 0; j < 8; j++) acc[i][j] = 0.f;

    for (int k0 = 0; k0 < K; k0 += 16) {
#pragma unroll
        for (int i = 0; i < 2; i++) {
            int s   = tid + i * 256;
            int row = s >> 2;
            int k4  = (s & 3) << 2;
            float4 av = *(const float4*)(A + (size_t)(bm + row) * K + k0 + k4);
            As[k4+0][row] = av.x; As[k4+1][row] = av.y;
            As[k4+2][row] = av.z; As[k4+3][row] = av.w;
            float4 wv = *(const float4*)(W + (size_t)(bn + row) * K + k0 + k4);
            Ws[k4+0][row] = wv.x; Ws[k4+1][row] = wv.y;
            Ws[k4+2][row] = wv.z; Ws[k4+3][row] = wv.w;
        }
        __syncthreads();
#pragma unroll
        for (int k = 0; k < 16; k++) {
            float af[8], bf[8];
            *(float4*)&af[0] = *(const float4*)&As[k][trow];
            *(float4*)&af[4] = *(const float4*)&As[k][trow + 4];
            *(float4*)&bf[0] = *(const float4*)&Ws[k][tcol];
            *(float4*)&bf[4] = *(const float4*)&Ws[k][tcol + 4];
#pragma unroll
            for (int i = 0; i < 8; i++)
#pragma unroll
                for (int j = 0; j < 8; j++)
                    acc[i][j] += af[i] * bf[j];
        }
        __syncthreads();
    }

#pragma unroll
    for (int j = 0; j < 8; j++) {
        int o = bn + tcol + j;
        float sc = gamma[o] * rsqrtf(var[o] + EPSV);
        float sh = beta[o] - mean[o] * sc;
        int h  = o / 384;
        int rr = o - h * 384;
#pragma unroll
        for (int i = 0; i < 8; i++) {
            int row = bm + trow + i;
            int b = row / Nseq;
            int n = row - b * Nseq;
            float val = acc[i][j] * sc + sh;
            size_t bhn = (size_t)(b * Hh + h) * Nseq + n;
            if (rr < KDIM)            g_Q[bhn * KDIM + rr] = val;
            else if (rr < 2 * KDIM)   g_K[bhn * KDIM + (rr - KDIM)] = val;
            else                      g_V[bhn * VDIM + (rr - 2 * KDIM)] = val;
        }
    }
}

// =====================================================================
// Attention: per (b,h), 32 query rows per CTA, online softmax over
// 25 key tiles of 32. Bias computed analytically; head bias row in smem.
// SiLU fused into epilogue; writes AO[b,n,h*256+d].
// dynamic smem = 57536 B
// =====================================================================
__global__ __launch_bounds__(256) void attn_kernel(const float* __restrict__ biases)
{
    extern __shared__ float smem[];
    float (*qs)[68]  = (float(*)[68])smem;                        // 2176 f
    float (*ks)[68]  = (float(*)[68])(smem + 32 * 68);            // 2176 f
    float (*vs)[256] = (float(*)[256])(smem + 2 * 32 * 68);       // 8192 f
    float (*ps)[33]  = (float(*)[33])(smem + 2 * 32 * 68 + 32 * 256); // 1056 f
    float* brow = smem + 2 * 32 * 68 + 32 * 256 + 32 * 33;        // 784 f

    int bh = blockIdx.y;           // b*8+h
    int b  = bh >> 3;
    int h  = bh & 7;
    int n0 = blockIdx.x * 32;
    int tid  = threadIdx.x;
    int lane = tid & 31;
    int w    = tid >> 5;

    const float* Qb = g_Q + (size_t)bh * Nseq * KDIM;
    const float* Kb = g_K + (size_t)bh * Nseq * KDIM;
    const float* Vb = g_V + (size_t)bh * Nseq * VDIM;

    for (int i = tid; i < Nseq; i += 256) brow[i] = biases[h * Nseq + i];

    // load Q tile 32x64
#pragma unroll
    for (int i = 0; i < 2; i++) {
        int s = tid + i * 256;
        int row = s >> 4;
        int c4  = (s & 15) << 2;
        int n = n0 + row;
        float4 qv = (n < Nseq) ? *(const float4*)(Qb + (size_t)n * KDIM + c4)
                               : make_float4(0.f, 0.f, 0.f, 0.f);
        *(float4*)&qs[row][c4] = qv;
    }

    float mrow[4], lrow[4], o[4][8];
    int ny[4], nx[4];
#pragma unroll
    for (int rr = 0; rr < 4; rr++) {
        mrow[rr] = -1e30f;
        lrow[rr] = 0.f;
#pragma unroll
        for (int t = 0; t < 8; t++) o[rr][t] = 0.f;
        int n = n0 + w * 4 + rr;
        int nc = (n < Nseq) ? n : (Nseq - 1);
        ny[rr] = nc / RESW;
        nx[rr] = nc - ny[rr] * RESW;
    }
    __syncthreads();

    for (int kt = 0; kt < 25; kt++) {
        int mbase = kt * 32;
        // load K tile 32x64
#pragma unroll
        for (int i = 0; i < 2; i++) {
            int s = tid + i * 256;
            int row = s >> 4;
            int c4  = (s & 15) << 2;
            int m = mbase + row;
            float4 kv = (m < Nseq) ? *(const float4*)(Kb + (size_t)m * KDIM + c4)
                                   : make_float4(0.f, 0.f, 0.f, 0.f);
            *(float4*)&ks[row][c4] = kv;
        }
        // load V tile 32x256
#pragma unroll
        for (int i = 0; i < 8; i++) {
            int s = tid + i * 256;
            int row = s >> 6;
            int c4  = (s & 63) << 2;
            int m = mbase + row;
            float4 vv = (m < Nseq) ? *(const float4*)(Vb + (size_t)m * VDIM + c4)
                                   : make_float4(0.f, 0.f, 0.f, 0.f);
            *(float4*)&vs[row][c4] = vv;
        }
        __syncthreads();

        int m = mbase + lane;
        bool mvalid = (m < Nseq);
        int mc = mvalid ? m : (Nseq - 1);
        int my = mc / RESW;
        int mx = mc - my * RESW;

#pragma unroll
        for (int rr = 0; rr < 4; rr++) {
            int r = w * 4 + rr;
            const float4* q4 = (const float4*)&qs[r][0];
            const float4* k4 = (const float4*)&ks[lane][0];
            float s = 0.f;
#pragma unroll
            for (int d4 = 0; d4 < 16; d4++) {
                float4 qv = q4[d4];
                float4 kv = k4[d4];
                s += qv.x * kv.x + qv.y * kv.y + qv.z * kv.z + qv.w * kv.w;
            }
            int dy = abs(ny[rr] - my), dx = abs(nx[rr] - mx);
            s = mvalid ? (s * SCALEV + brow[dy * RESW + dx]) : -1e30f;

            float tmax = s;
#pragma unroll
            for (int off = 16; off; off >>= 1)
                tmax = fmaxf(tmax, __shfl_xor_sync(0xffffffffu, tmax, off));
            float mnew = fmaxf(mrow[rr], tmax);
            float p = __expf(s - mnew);
            if (!mvalid) p = 0.f;
            float psum = p;
#pragma unroll
            for (int off = 16; off; off >>= 1)
                psum += __shfl_xor_sync(0xffffffffu, psum, off);
            float corr = __expf(mrow[rr] - mnew);
            lrow[rr] = lrow[rr] * corr + psum;
            mrow[rr] = mnew;
            ps[r][lane] = p;
#pragma unroll
            for (int t = 0; t < 8; t++) o[rr][t] *= corr;
        }
        __syncwarp();

        // PV: register-blocked over m (V row reused across 4 query rows)
#pragma unroll 4
        for (int mm = 0; mm < 32; mm++) {
            float vv[8];
#pragma unroll
            for (int t = 0; t < 8; t++) vv[t] = vs[mm][lane + 32 * t];
#pragma unroll
            for (int rr = 0; rr < 4; rr++) {
                float p = ps[w * 4 + rr][mm];
#pragma unroll
                for (int t = 0; t < 8; t++) o[rr][t] += p * vv[t];
            }
        }
        __syncthreads();
    }

    // epilogue: normalize, SiLU, store
#pragma unroll
    for (int rr = 0; rr < 4; rr++) {
        int n = n0 + w * 4 + rr;
        if (n < Nseq) {
            float inv = 1.f / lrow[rr];
            size_t base = ((size_t)b * Nseq + n) * (Hh * VDIM) + h * VDIM;
#pragma unroll
            for (int t = 0; t < 8; t++) {
                float x = o[rr][t] * inv;
                float si = x / (1.f + __expf(-x));
                g_AO[base + lane + 32 * t] = si;
            }
        }
    }
}

// =====================================================================
// GEMM 2: out = BN(silu_out @ proj_w^T); M=12544, N=512, K=2048
// =====================================================================
__global__ __launch_bounds__(256) void gemm_proj_kernel(
    const float* __restrict__ W,
    const float* __restrict__ gamma, const float* __restrict__ beta,
    const float* __restrict__ mean, const float* __restrict__ var,
    float* __restrict__ out)
{
    __shared__ float As[16][132];
    __shared__ float Ws[16][132];
    const int K = Hh * VDIM;   // 2048
    const float* A = g_AO;
    int bm = blockIdx.x * 128;
    int bn = blockIdx.y * 128;
    int tid = threadIdx.x;
    int trow = (tid >> 4) << 3;
    int tcol = (tid & 15) << 3;

    float acc[8][8];
#pragma unroll
    for (int i = 0; i < 8; i++)
#pragma unroll
        for (int j = 0; j < 8; j++) acc[i][j] = 0.f;

    for (int k0 = 0; k0 < K; k0 += 16) {
#pragma unroll
        for (int i = 0; i < 2; i++) {
            int s   = tid + i * 256;
            int row = s >> 2;
            int k4  = (s & 3) << 2;
            float4 av = *(const float4*)(A + (size_t)(bm + row) * K + k0 + k4);
            As[k4+0][row] = av.x; As[k4+1][row] = av.y;
            As[k4+2][row] = av.z; As[k4+3][row] = av.w;
            float4 wv = *(const float4*)(W + (size_t)(bn + row) * K + k0 + k4);
            Ws[k4+0][row] = wv.x; Ws[k4+1][row] = wv.y;
            Ws[k4+2][row] = wv.z; Ws[k4+3][row] = wv.w;
        }
        __syncthreads();
#pragma unroll
        for (int k = 0; k < 16; k++) {
            float af[8], bf[8];
            *(float4*)&af[0] = *(const float4*)&As[k][trow];
            *(float4*)&af[4] = *(const float4*)&As[k][trow + 4];
            *(float4*)&bf[0] = *(const float4*)&Ws[k][tcol];
            *(float4*)&bf[4] = *(const float4*)&Ws[k][tcol + 4];
#pragma unroll
            for (int i = 0; i < 8; i++)
#pragma unroll
                for (int j = 0; j < 8; j++)
                    acc[i][j] += af[i] * bf[j];
        }
        __syncthreads();
    }

#pragma unroll
    for (int j = 0; j < 8; j++) {
        int o = bn + tcol + j;
        float sc = gamma[o] * rsqrtf(var[o] + EPSV);
        float sh = beta[o] - mean[o] * sc;
#pragma unroll
        for (int i = 0; i < 8; i++) {
            int row = bm + trow + i;
            out[(size_t)row * DIM + o] = acc[i][j] * sc + sh;
        }
    }
}

// =====================================================================
extern "C" void kernel_launch(void* const* d_in, const int* in_sizes, int n_in,
                              void* d_out, int out_size)
{
    const float* x          = (const float*)d_in[0];
    const float* qkv_w      = (const float*)d_in[1];
    const float* qkv_gamma  = (const float*)d_in[2];
    const float* qkv_beta   = (const float*)d_in[3];
    const float* qkv_mean   = (const float*)d_in[4];
    const float* qkv_var    = (const float*)d_in[5];
    const float* att_bias   = (const float*)d_in[6];
    const float* proj_w     = (const float*)d_in[7];
    const float* proj_gamma = (const float*)d_in[8];
    const float* proj_beta  = (const float*)d_in[9];
    const float* proj_mean  = (const float*)d_in[10];
    const float* proj_var   = (const float*)d_in[11];
    // d_in[12] = bias_idxs: computed analytically in-kernel (identical formula)

    cudaFuncSetAttribute(attn_kernel,
                         cudaFuncAttributeMaxDynamicSharedMemorySize, 57536);

    gemm_qkv_kernel<<<dim3(Mrows / 128, QKVO / 128), 256>>>(
        x, qkv_w, qkv_gamma, qkv_beta, qkv_mean, qkv_var);

    attn_kernel<<<dim3(25, Bsz * Hh), 256, 57536>>>(att_bias);

    gemm_proj_kernel<<<dim3(Mrows / 128, DIM / 128), 256>>>(
        proj_w, proj_gamma, proj_beta, proj_mean, proj_var, (float*)d_out);
}

// round 3
// speedup vs baseline: 1.1837x; 1.1837x over previous
#include <cuda_runtime.h>
#include <math.h>

// ---------------- problem constants ----------------
#define Bsz   16
#define Nseq  784
#define DIM   512
#define Hh    8
#define KDIM  64
#define VDIM  256
#define RESW  28
#define QKVO  3072      // (2*64+256)*8
#define Mrows (Bsz*Nseq) // 12544
#define EPSV  1e-5f
#define SCALEV 0.125f    // 64^-0.5

// ---------------- scratch (device globals; no allocs allowed) ----------------
// Q, K stored TRANSPOSED per (b,h):  [bh][d][n]   (d-major for attn smem loads)
__device__ float g_Q[(size_t)Bsz*Hh*KDIM*Nseq];
__device__ float g_K[(size_t)Bsz*Hh*KDIM*Nseq];
__device__ float g_V[(size_t)Bsz*Hh*Nseq*VDIM];
__device__ float g_AO[(size_t)Bsz*Nseq*Hh*VDIM];

// =====================================================================
// GEMM 1: qkv = BN(x @ qkv_w^T) -> scatter to Q^T/K^T/V
// =====================================================================
__global__ __launch_bounds__(256) void gemm_qkv_kernel(
    const float* __restrict__ A, const float* __restrict__ W,
    const float* __restrict__ gamma, const float* __restrict__ beta,
    const float* __restrict__ mean, const float* __restrict__ var)
{
    __shared__ float As[16][132];
    __shared__ float Ws[16][132];
    const int K = DIM;
    int bm = blockIdx.x * 128;
    int bn = blockIdx.y * 128;
    int tid = threadIdx.x;
    int trow = (tid >> 4) << 3;
    int tcol = (tid & 15) << 3;

    float acc[8][8];
#pragma unroll
    for (int i = 0; i < 8; i++)
#pragma unroll
        for (int j = 0; j < 8; j++) acc[i][j] = 0.f;

    for (int k0 = 0; k0 < K; k0 += 16) {
#pragma unroll
        for (int i = 0; i < 2; i++) {
            int s   = tid + i * 256;
            int row = s >> 2;
            int k4  = (s & 3) << 2;
            float4 av = *(const float4*)(A + (size_t)(bm + row) * K + k0 + k4);
            As[k4+0][row] = av.x; As[k4+1][row] = av.y;
            As[k4+2][row] = av.z; As[k4+3][row] = av.w;
            float4 wv = *(const float4*)(W + (size_t)(bn + row) * K + k0 + k4);
            Ws[k4+0][row] = wv.x; Ws[k4+1][row] = wv.y;
            Ws[k4+2][row] = wv.z; Ws[k4+3][row] = wv.w;
        }
        __syncthreads();
#pragma unroll
        for (int k = 0; k < 16; k++) {
            float af[8], bf[8];
            *(float4*)&af[0] = *(const float4*)&As[k][trow];
            *(float4*)&af[4] = *(const float4*)&As[k][trow + 4];
            *(float4*)&bf[0] = *(const float4*)&Ws[k][tcol];
            *(float4*)&bf[4] = *(const float4*)&Ws[k][tcol + 4];
#pragma unroll
            for (int i = 0; i < 8; i++)
#pragma unroll
                for (int j = 0; j < 8; j++)
                    acc[i][j] += af[i] * bf[j];
        }
        __syncthreads();
    }

#pragma unroll
    for (int j = 0; j < 8; j++) {
        int o = bn + tcol + j;
        float sc = gamma[o] * rsqrtf(var[o] + EPSV);
        float sh = beta[o] - mean[o] * sc;
        int h  = o / 384;
        int rr = o - h * 384;
#pragma unroll
        for (int i = 0; i < 8; i++) {
            int row = bm + trow + i;
            int b = row / Nseq;
            int n = row - b * Nseq;
            float val = acc[i][j] * sc + sh;
            int bh = b * Hh + h;
            if (rr < KDIM)
                g_Q[((size_t)bh * KDIM + rr) * Nseq + n] = val;
            else if (rr < 2 * KDIM)
                g_K[((size_t)bh * KDIM + (rr - KDIM)) * Nseq + n] = val;
            else
                g_V[((size_t)bh * Nseq + n) * VDIM + (rr - 2 * KDIM)] = val;
        }
    }
}

// =====================================================================
// Attention v2.1: flash-style, two register-blocked GEMMs.
// (v2 bug fixed: Q/K tile loads now cover all 64 dims — i<4, not i<2)
// CTA: 256 thr, 64 q rows, key tiles of 64, V chunked 2x128.
//   S-stage: 4x4 microtile over transposed Q/K tiles.
//   PV-stage: 8x8 microtile (rows x vcols), P broadcast from smem.
// Bias computed analytically; SiLU fused. smem = 88896 B.
// =====================================================================
#define ATT_SMEM 88896
__global__ __launch_bounds__(256, 2) void attn_kernel(const float* __restrict__ biases)
{
    extern __shared__ float smem[];
    float (*Qst)[68]  = (float(*)[68])smem;                 // [64 d][64 rows+pad]
    float (*Kst)[68]  = (float(*)[68])(smem + 4352);        // [64 d][64 keys+pad]
    float (*Ps)[68]   = (float(*)[68])(smem + 8704);        // [64 rows][64 keys+pad]
    float (*Vs)[128]  = (float(*)[128])(smem + 13056);      // [64 keys][128 vcols]
    float* brow = smem + 21248;                             // 784
    float* marr = smem + 22032;                             // 64
    float* larr = smem + 22096;                             // 64
    float* carr = smem + 22160;                             // 64

    const int bh = blockIdx.y;          // b*8+h
    const int b  = bh >> 3;
    const int h  = bh & 7;
    const int n0 = blockIdx.x * 64;
    const int tid  = threadIdx.x;
    const int lane = tid & 31;
    const int w    = tid >> 5;

    const float* Qb = g_Q + (size_t)bh * KDIM * Nseq;
    const float* Kb = g_K + (size_t)bh * KDIM * Nseq;
    const float* Vb = g_V + (size_t)bh * Nseq * VDIM;

    // bias row for this head
    for (int i = tid; i < Nseq; i += 256) brow[i] = biases[h * Nseq + i];
    if (tid < 64) { marr[tid] = -1e30f; larr[tid] = 0.f; }

    // load Q^T tile: Qst[d][r] from g_Q[bh][d][n0+r]   (64 d x 64 rows)
#pragma unroll
    for (int i = 0; i < 4; i++) {
        int s  = tid + i * 256;
        int d  = s >> 4;
        int q4 = (s & 15) << 2;
        float4 v = (n0 + q4 < Nseq)
                 ? *(const float4*)(Qb + (size_t)d * Nseq + n0 + q4)
                 : make_float4(0.f, 0.f, 0.f, 0.f);
        *(float4*)&Qst[d][q4] = v;
    }

    // S mapping: rows sr..sr+3, keys sc..sc+3
    const int sr = (tid >> 4) << 2;
    const int sc = (tid & 15) << 2;
    // PV mapping: rows ro..ro+7, vcols: lane*4 (chunk0) & 128+lane*4 (chunk1)
    const int ro = w << 3;
    const int co = lane << 2;

    // precompute row positions for bias
    int ry[4], rx[4];
#pragma unroll
    for (int i = 0; i < 4; i++) {
        int n = n0 + sr + i;
        int nc = (n < Nseq) ? n : (Nseq - 1);
        ry[i] = nc / RESW;
        rx[i] = nc - ry[i] * RESW;
    }

    float o[8][8];
#pragma unroll
    for (int i = 0; i < 8; i++)
#pragma unroll
        for (int j = 0; j < 8; j++) o[i][j] = 0.f;

    const int NTILE = (Nseq + 63) / 64;   // 13
    for (int kt = 0; kt < NTILE; kt++) {
        const int mbase = kt * 64;
        __syncthreads();   // protect Kst/Vs reuse

        // load K^T tile: Kst[d][m] from g_K[bh][d][mbase+m]   (64 d x 64 keys)
#pragma unroll
        for (int i = 0; i < 4; i++) {
            int s  = tid + i * 256;
            int d  = s >> 4;
            int q4 = (s & 15) << 2;
            float4 v = (mbase + q4 < Nseq)
                     ? *(const float4*)(Kb + (size_t)d * Nseq + mbase + q4)
                     : make_float4(0.f, 0.f, 0.f, 0.f);
            *(float4*)&Kst[d][q4] = v;
        }
        __syncthreads();

        // ---- S = Q.K^T (4x4 microtile) ----
        float s4[4][4];
#pragma unroll
        for (int i = 0; i < 4; i++)
#pragma unroll
            for (int j = 0; j < 4; j++) s4[i][j] = 0.f;
#pragma unroll
        for (int d = 0; d < KDIM; d++) {
            float4 qv = *(const float4*)&Qst[d][sr];   // broadcast across 16 lanes
            float4 kv = *(const float4*)&Kst[d][sc];
            float qa[4] = {qv.x, qv.y, qv.z, qv.w};
            float ka[4] = {kv.x, kv.y, kv.z, kv.w};
#pragma unroll
            for (int i = 0; i < 4; i++)
#pragma unroll
                for (int j = 0; j < 4; j++)
                    s4[i][j] += qa[i] * ka[j];
        }

        // bias + mask
        int myv[4], mxv[4];
        bool mval[4];
#pragma unroll
        for (int j = 0; j < 4; j++) {
            int m = mbase + sc + j;
            mval[j] = (m < Nseq);
            int mc = mval[j] ? m : (Nseq - 1);
            myv[j] = mc / RESW;
            mxv[j] = mc - myv[j] * RESW;
        }
#pragma unroll
        for (int i = 0; i < 4; i++)
#pragma unroll
            for (int j = 0; j < 4; j++) {
                int dy = abs(ry[i] - myv[j]);
                int dx = abs(rx[i] - mxv[j]);
                s4[i][j] = mval[j] ? (s4[i][j] * SCALEV + brow[dy * RESW + dx])
                                   : -1e30f;
            }

        // ---- online softmax (rows shared by 16 contiguous lanes) ----
#pragma unroll
        for (int i = 0; i < 4; i++) {
            int r = sr + i;
            float tmax = fmaxf(fmaxf(s4[i][0], s4[i][1]), fmaxf(s4[i][2], s4[i][3]));
#pragma unroll
            for (int off = 8; off; off >>= 1)
                tmax = fmaxf(tmax, __shfl_xor_sync(0xffffffffu, tmax, off));
            float mold = marr[r];
            float mnew = fmaxf(mold, tmax);
            float psum = 0.f;
#pragma unroll
            for (int j = 0; j < 4; j++) {
                float p = __expf(s4[i][j] - mnew);
                Ps[r][sc + j] = p;
                psum += p;
            }
#pragma unroll
            for (int off = 8; off; off >>= 1)
                psum += __shfl_xor_sync(0xffffffffu, psum, off);
            if ((tid & 15) == 0) {
                float corr = __expf(mold - mnew);
                larr[r] = larr[r] * corr + psum;
                marr[r] = mnew;
                carr[r] = corr;
            }
        }
        __syncthreads();

        // rescale O by row correction
#pragma unroll
        for (int i = 0; i < 8; i++) {
            float corr = carr[ro + i];
#pragma unroll
            for (int j = 0; j < 8; j++) o[i][j] *= corr;
        }

        // ---- PV over 2 vcol chunks of 128 ----
#pragma unroll
        for (int c = 0; c < 2; c++) {
            // load V chunk: Vs[m][cc] = V[mbase+m][c*128+cc]
#pragma unroll
            for (int i = 0; i < 8; i++) {
                int s  = tid + i * 256;
                int mm = s >> 5;
                int c4 = (s & 31) << 2;
                float4 v = (mbase + mm < Nseq)
                         ? *(const float4*)(Vb + (size_t)(mbase + mm) * VDIM + c * 128 + c4)
                         : make_float4(0.f, 0.f, 0.f, 0.f);
                *(float4*)&Vs[mm][c4] = v;
            }
            __syncthreads();

#pragma unroll 4
            for (int mm = 0; mm < 64; mm++) {
                float4 vv = *(const float4*)&Vs[mm][co];
                float va[4] = {vv.x, vv.y, vv.z, vv.w};
#pragma unroll
                for (int i = 0; i < 8; i++) {
                    float p = Ps[ro + i][mm];       // warp broadcast
#pragma unroll
                    for (int j = 0; j < 4; j++)
                        o[i][c * 4 + j] += p * va[j];
                }
            }
            __syncthreads();
        }
    }

    // ---- epilogue: normalize, SiLU, store ----
#pragma unroll
    for (int i = 0; i < 8; i++) {
        int n = n0 + ro + i;
        if (n < Nseq) {
            float inv = 1.f / larr[ro + i];
            size_t base = ((size_t)b * Nseq + n) * (Hh * VDIM) + h * VDIM;
            float4 v0, v1;
            float t;
            t = o[i][0] * inv; v0.x = t / (1.f + __expf(-t));
            t = o[i][1] * inv; v0.y = t / (1.f + __expf(-t));
            t = o[i][2] * inv; v0.z = t / (1.f + __expf(-t));
            t = o[i][3] * inv; v0.w = t / (1.f + __expf(-t));
            t = o[i][4] * inv; v1.x = t / (1.f + __expf(-t));
            t = o[i][5] * inv; v1.y = t / (1.f + __expf(-t));
            t = o[i][6] * inv; v1.z = t / (1.f + __expf(-t));
            t = o[i][7] * inv; v1.w = t / (1.f + __expf(-t));
            *(float4*)(g_AO + base + co)       = v0;
            *(float4*)(g_AO + base + 128 + co) = v1;
        }
    }
}

// =====================================================================
// GEMM 2: out = BN(silu_out @ proj_w^T); M=12544, N=512, K=2048
// =====================================================================
__global__ __launch_bounds__(256) void gemm_proj_kernel(
    const float* __restrict__ W,
    const float* __restrict__ gamma, const float* __restrict__ beta,
    const float* __restrict__ mean, const float* __restrict__ var,
    float* __restrict__ out)
{
    __shared__ float As[16][132];
    __shared__ float Ws[16][132];
    const int K = Hh * VDIM;   // 2048
    const float* A = g_AO;
    int bm = blockIdx.x * 128;
    int bn = blockIdx.y * 128;
    int tid = threadIdx.x;
    int trow = (tid >> 4) << 3;
    int tcol = (tid & 15) << 3;

    float acc[8][8];
#pragma unroll
    for (int i = 0; i < 8; i++)
#pragma unroll
        for (int j = 0; j < 8; j++) acc[i][j] = 0.f;

    for (int k0 = 0; k0 < K; k0 += 16) {
#pragma unroll
        for (int i = 0; i < 2; i++) {
            int s   = tid + i * 256;
            int row = s >> 2;
            int k4  = (s & 3) << 2;
            float4 av = *(const float4*)(A + (size_t)(bm + row) * K + k0 + k4);
            As[k4+0][row] = av.x; As[k4+1][row] = av.y;
            As[k4+2][row] = av.z; As[k4+3][row] = av.w;
            float4 wv = *(const float4*)(W + (size_t)(bn + row) * K + k0 + k4);
            Ws[k4+0][row] = wv.x; Ws[k4+1][row] = wv.y;
            Ws[k4+2][row] = wv.z; Ws[k4+3][row] = wv.w;
        }
        __syncthreads();
#pragma unroll
        for (int k = 0; k < 16; k++) {
            float af[8], bf[8];
            *(float4*)&af[0] = *(const float4*)&As[k][trow];
            *(float4*)&af[4] = *(const float4*)&As[k][trow + 4];
            *(float4*)&bf[0] = *(const float4*)&Ws[k][tcol];
            *(float4*)&bf[4] = *(const float4*)&Ws[k][tcol + 4];
#pragma unroll
            for (int i = 0; i < 8; i++)
#pragma unroll
                for (int j = 0; j < 8; j++)
                    acc[i][j] += af[i] * bf[j];
        }
        __syncthreads();
    }

#pragma unroll
    for (int j = 0; j < 8; j++) {
        int o = bn + tcol + j;
        float sc = gamma[o] * rsqrtf(var[o] + EPSV);
        float sh = beta[o] - mean[o] * sc;
#pragma unroll
        for (int i = 0; i < 8; i++) {
            int row = bm + trow + i;
            out[(size_t)row * DIM + o] = acc[i][j] * sc + sh;
        }
    }
}

// =====================================================================
extern "C" void kernel_launch(void* const* d_in, const int* in_sizes, int n_in,
                              void* d_out, int out_size)
{
    const float* x          = (const float*)d_in[0];
    const float* qkv_w      = (const float*)d_in[1];
    const float* qkv_gamma  = (const float*)d_in[2];
    const float* qkv_beta   = (const float*)d_in[3];
    const float* qkv_mean   = (const float*)d_in[4];
    const float* qkv_var    = (const float*)d_in[5];
    const float* att_bias   = (const float*)d_in[6];
    const float* proj_w     = (const float*)d_in[7];
    const float* proj_gamma = (const float*)d_in[8];
    const float* proj_beta  = (const float*)d_in[9];
    const float* proj_mean  = (const float*)d_in[10];
    const float* proj_var   = (const float*)d_in[11];
    // d_in[12] = bias_idxs: computed analytically in-kernel (identical formula)

    cudaFuncSetAttribute(attn_kernel,
                         cudaFuncAttributeMaxDynamicSharedMemorySize, ATT_SMEM);

    gemm_qkv_kernel<<<dim3(Mrows / 128, QKVO / 128), 256>>>(
        x, qkv_w, qkv_gamma, qkv_beta, qkv_mean, qkv_var);

    attn_kernel<<<dim3((Nseq + 63) / 64, Bsz * Hh), 256, ATT_SMEM>>>(att_bias);

    gemm_proj_kernel<<<dim3(Mrows / 128, DIM / 128), 256>>>(
        proj_w, proj_gamma, proj_beta, proj_mean, proj_var, (float*)d_out);
}